// round 8
// baseline (speedup 1.0000x reference)
#include <cuda_runtime.h>
#include <cuda_bf16.h>
#include <cstdint>

// out[b,p,l] = w_in[p, x[b,l]];  B=64, L=4096, P=128, VOCAB=32000, fp32.
#define PB   128
#define VOC  32000
#define BB   64
#define LL   4096
#define TOK  32            // tokens per gather block
#define PITCH_B 528        // smem row pitch: 512 B + 16 B pad = 33 float4 (odd)
#define PITCH_F4 33

// Transposed weight table w_t[v][p] (16.38 MB, mostly L2-resident).
__device__ __align__(512) float g_wt[(size_t)VOC * PB];

// ---------------- PTX helpers ----------------
__device__ __forceinline__ uint32_t smem_u32(const void* p) {
    return (uint32_t)__cvta_generic_to_shared(p);
}
__device__ __forceinline__ void mbar_init(uint32_t mbar, uint32_t cnt) {
    asm volatile("mbarrier.init.shared.b64 [%0], %1;" :: "r"(mbar), "r"(cnt) : "memory");
}
__device__ __forceinline__ void mbar_expect_tx(uint32_t mbar, uint32_t bytes) {
    asm volatile("mbarrier.arrive.expect_tx.shared.b64 _, [%0], %1;"
                 :: "r"(mbar), "r"(bytes) : "memory");
}
__device__ __forceinline__ void mbar_wait(uint32_t mbar, uint32_t parity) {
    asm volatile(
        "{\n\t"
        ".reg .pred P1;\n\t"
        "WAIT_LOOP_%=:\n\t"
        "mbarrier.try_wait.parity.acquire.cta.shared::cta.b64 P1, [%0], %1, 0x989680;\n\t"
        "@P1 bra.uni WAIT_DONE_%=;\n\t"
        "bra.uni WAIT_LOOP_%=;\n\t"
        "WAIT_DONE_%=:\n\t"
        "}"
        :: "r"(mbar), "r"(parity) : "memory");
}
__device__ __forceinline__ void bulk_g2s(uint32_t dst_smem, const void* src_gmem,
                                         uint32_t bytes, uint32_t mbar) {
    asm volatile(
        "cp.async.bulk.shared::cluster.global.mbarrier::complete_tx::bytes "
        "[%0], [%1], %2, [%3];"
        :: "r"(dst_smem), "l"(src_gmem), "r"(bytes), "r"(mbar) : "memory");
}
__device__ __forceinline__ void pdl_trigger() {
    asm volatile("griddepcontrol.launch_dependents;" ::: "memory");
}
__device__ __forceinline__ void pdl_wait() {
    asm volatile("griddepcontrol.wait;" ::: "memory");
}

// ---------------------------------------------------------------------------
// Kernel A: transpose w_in(P, VOC) -> g_wt(VOC, P).  Zero smem, zero sync.
// Grid (250, 4): block covers 128 v x 32 p. Warp w owns p-quad p0 = by*32+4w;
// lane owns v-quad v0 + 4*lane. 4x coalesced LDG.128 reads, 4x4 register
// transpose, 4x STG.128 16 B-scatter writes (sector halves merged in L2 by
// the neighbor warp of the same block). Ends with fence + PDL trigger.
// ---------------------------------------------------------------------------
__global__ __launch_bounds__(256) void transpose_kernel(const float* __restrict__ w_in) {
    const int lane = threadIdx.x & 31;
    const int wrp  = threadIdx.x >> 5;           // 0..7
    const int v0   = blockIdx.x * 128;
    const int p0   = blockIdx.y * 32 + 4 * wrp;
    const int v    = v0 + 4 * lane;

    const size_t base = (size_t)p0 * VOC + v;
    const float4 a0 = *reinterpret_cast<const float4*>(&w_in[base]);
    const float4 a1 = *reinterpret_cast<const float4*>(&w_in[base + (size_t)VOC]);
    const float4 a2 = *reinterpret_cast<const float4*>(&w_in[base + 2 * (size_t)VOC]);
    const float4 a3 = *reinterpret_cast<const float4*>(&w_in[base + 3 * (size_t)VOC]);

    float4* __restrict__ dst = reinterpret_cast<float4*>(&g_wt[(size_t)v * PB + p0]);
    const size_t rs = PB / 4;                    // f4 stride between v-rows
    dst[0]      = make_float4(a0.x, a1.x, a2.x, a3.x);   // v
    dst[rs]     = make_float4(a0.y, a1.y, a2.y, a3.y);   // v+1
    dst[2 * rs] = make_float4(a0.z, a1.z, a2.z, a3.z);   // v+2
    dst[3 * rs] = make_float4(a0.w, a1.w, a2.w, a3.w);   // v+3

    // Make g_wt writes GPU-visible, then allow the gather grid to proceed.
    __threadfence();
    pdl_trigger();
}

// ---------------------------------------------------------------------------
// Kernel B: gather. Block: 128 threads, (b = blockIdx.y, 32 tokens).
// Launched with PDL: prologue (mbar init, x loads) overlaps the transpose;
// griddepcontrol.wait gates only the TMA reads of g_wt.
// Token t (g=t>>2, j=t&3) lands at smem row R = 2g + (j&1) + 16*(j>>1).
// Two mbarriers (tokens 0..15 / 16..31, 8 KB halves), all TMA up front.
// Phase 2 half h: thread (g = 4h + (lane&3), q = wrp*8 + (lane>>2)):
//   4x conflict-free LDS.128, 4x4 register transpose, 4x STG.128 (__stcs).
// ---------------------------------------------------------------------------
__global__ __launch_bounds__(128) void gather_kernel(
    const int* __restrict__ x, float* __restrict__ out) {
    __shared__ __align__(16) float tile[TOK * PITCH_F4 * 4];
    __shared__ __align__(8) unsigned long long mbar_storage[2];
    const float4* s4 = reinterpret_cast<const float4*>(tile);
    const uint32_t mbar0 = smem_u32(&mbar_storage[0]);
    const uint32_t mbar1 = smem_u32(&mbar_storage[1]);

    const int tid  = threadIdx.x;
    const int lane = tid & 31;
    const int wrp  = tid >> 5;
    const int b    = blockIdx.y;
    const int l0   = blockIdx.x * TOK;

    if (tid == 0) { mbar_init(mbar0, 1); mbar_init(mbar1, 1); }
    __syncthreads();
    if (tid == 0) {
        mbar_expect_tx(mbar0, 16 * 512);
        mbar_expect_tx(mbar1, 16 * 512);
    }

    int v = 0, R = 0;
    if (tid < TOK) {
        v = x[(size_t)b * LL + l0 + tid];        // independent of transpose
        const int g = tid >> 2, j = tid & 3;
        R = 2 * g + (j & 1) + 16 * (j >> 1);
    }

    pdl_wait();                                  // g_wt ready past this point

    if (tid < TOK) {
        bulk_g2s(smem_u32(tile) + R * PITCH_B, &g_wt[(size_t)v * PB], 512,
                 tid < 16 ? mbar0 : mbar1);
    }

    const int gl = lane & 3;                     // token-group within half
    const int q  = wrp * 8 + (lane >> 2);        // p-quad 0..31
    float4* __restrict__ out4 = reinterpret_cast<float4*>(out);
    const size_t rstride = LL / 4;               // float4s per p-row

    #pragma unroll
    for (int h = 0; h < 2; h++) {
        mbar_wait(h == 0 ? mbar0 : mbar1, 0);
        const int g = h * 4 + gl;                // token group (tokens 4g..4g+3)
        const int r0 = 2 * g;
        float4 f0 = s4[(r0 + 0)  * PITCH_F4 + q];   // j=0
        float4 f1 = s4[(r0 + 1)  * PITCH_F4 + q];   // j=1
        float4 f2 = s4[(r0 + 16) * PITCH_F4 + q];   // j=2
        float4 f3 = s4[(r0 + 17) * PITCH_F4 + q];   // j=3
        // Transpose: oj = tokens {4g..4g+3} at p = 4q+j.
        float4 o0 = make_float4(f0.x, f1.x, f2.x, f3.x);
        float4 o1 = make_float4(f0.y, f1.y, f2.y, f3.y);
        float4 o2 = make_float4(f0.z, f1.z, f2.z, f3.z);
        float4 o3 = make_float4(f0.w, f1.w, f2.w, f3.w);
        const size_t obase = ((size_t)b * PB + 4 * q) * rstride + (l0 >> 2) + g;
        __stcs(&out4[obase],               o0);
        __stcs(&out4[obase + rstride],     o1);
        __stcs(&out4[obase + 2 * rstride], o2);
        __stcs(&out4[obase + 3 * rstride], o3);
    }
}

// ---------------------------------------------------------------------------
// Launch: transpose, then gather with Programmatic Dependent Launch so the
// gather grid ramps (prologue) while the transpose drains.
// ---------------------------------------------------------------------------
extern "C" void kernel_launch(void* const* d_in, const int* in_sizes, int n_in,
                              void* d_out, int out_size) {
    const int*   x    = (const int*)d_in[0];     // (64, 4096) int32
    const float* w_in = (const float*)d_in[1];   // (128, 32000) fp32
    float*       out  = (float*)d_out;           // (64, 128, 4096) fp32
    (void)in_sizes; (void)n_in; (void)out_size;

    transpose_kernel<<<dim3(VOC / 128, 4), 256>>>(w_in);

    cudaLaunchConfig_t cfg = {};
    cfg.gridDim  = dim3(LL / TOK, BB);
    cfg.blockDim = dim3(128);
    cfg.dynamicSmemBytes = 0;
    cfg.stream = 0;
    cudaLaunchAttribute attrs[1];
    attrs[0].id = cudaLaunchAttributeProgrammaticStreamSerialization;
    attrs[0].val.programmaticStreamSerializationAllowed = 1;
    cfg.attrs = attrs;
    cfg.numAttrs = 1;
    cudaLaunchKernelEx(&cfg, gather_kernel, x, out);
}

// round 9
// speedup vs baseline: 1.2456x; 1.2456x over previous
#include <cuda_runtime.h>
#include <cuda_bf16.h>
#include <cstdint>

// out[b,p,l] = w_in[p, x[b,l]];  B=64, L=4096, P=128, VOCAB=32000, fp32.
#define PB   128
#define VOC  32000
#define BB   64
#define LL   4096
#define TOK  32            // tokens per gather block
#define PITCH_B 528        // smem row pitch: 512 B + 16 B pad = 33 float4 (odd)
#define PITCH_F4 33

// Transposed weight table w_t[v][p] (16.38 MB, mostly L2-resident).
__device__ __align__(512) float g_wt[(size_t)VOC * PB];

// ---------------- PTX helpers ----------------
__device__ __forceinline__ uint32_t smem_u32(const void* p) {
    return (uint32_t)__cvta_generic_to_shared(p);
}
__device__ __forceinline__ void mbar_init(uint32_t mbar, uint32_t cnt) {
    asm volatile("mbarrier.init.shared.b64 [%0], %1;" :: "r"(mbar), "r"(cnt) : "memory");
}
__device__ __forceinline__ void mbar_expect_tx(uint32_t mbar, uint32_t bytes) {
    asm volatile("mbarrier.arrive.expect_tx.shared.b64 _, [%0], %1;"
                 :: "r"(mbar), "r"(bytes) : "memory");
}
__device__ __forceinline__ void mbar_wait(uint32_t mbar, uint32_t parity) {
    asm volatile(
        "{\n\t"
        ".reg .pred P1;\n\t"
        "WAIT_LOOP_%=:\n\t"
        "mbarrier.try_wait.parity.acquire.cta.shared::cta.b64 P1, [%0], %1, 0x989680;\n\t"
        "@P1 bra.uni WAIT_DONE_%=;\n\t"
        "bra.uni WAIT_LOOP_%=;\n\t"
        "WAIT_DONE_%=:\n\t"
        "}"
        :: "r"(mbar), "r"(parity) : "memory");
}
// Bulk G2S with L2 evict-last hint: bias g_wt lines to stay resident against
// the streaming output writes.
__device__ __forceinline__ void bulk_g2s_el(uint32_t dst_smem, const void* src_gmem,
                                            uint32_t bytes, uint32_t mbar) {
    asm volatile(
        "{\n\t"
        ".reg .b64 policy;\n\t"
        "createpolicy.fractional.L2::evict_last.b64 policy, 1.0;\n\t"
        "cp.async.bulk.shared::cluster.global.mbarrier::complete_tx::bytes.L2::cache_hint "
        "[%0], [%1], %2, [%3], policy;\n\t"
        "}"
        :: "r"(dst_smem), "l"(src_gmem), "r"(bytes), "r"(mbar) : "memory");
}

// ---------------------------------------------------------------------------
// Kernel A: transpose w_in(P, VOC) -> g_wt(VOC, P).  Zero smem, zero sync.
// Grid (250, 4): block covers 128 v x 32 p. Warp w owns p-quad p0 = by*32+4w;
// lane owns v-quad v0 + 4*lane. 4x coalesced LDG.128 reads, 4x4 register
// transpose, 4x STG.128 16 B-scatter writes (sector halves merged in L2 by
// the neighbor warp of the same block).
// ---------------------------------------------------------------------------
__global__ __launch_bounds__(256) void transpose_kernel(const float* __restrict__ w_in) {
    const int lane = threadIdx.x & 31;
    const int wrp  = threadIdx.x >> 5;           // 0..7
    const int v0   = blockIdx.x * 128;
    const int p0   = blockIdx.y * 32 + 4 * wrp;
    const int v    = v0 + 4 * lane;

    const size_t base = (size_t)p0 * VOC + v;
    const float4 a0 = *reinterpret_cast<const float4*>(&w_in[base]);
    const float4 a1 = *reinterpret_cast<const float4*>(&w_in[base + (size_t)VOC]);
    const float4 a2 = *reinterpret_cast<const float4*>(&w_in[base + 2 * (size_t)VOC]);
    const float4 a3 = *reinterpret_cast<const float4*>(&w_in[base + 3 * (size_t)VOC]);

    float4* __restrict__ dst = reinterpret_cast<float4*>(&g_wt[(size_t)v * PB + p0]);
    const size_t rs = PB / 4;                    // f4 stride between v-rows
    dst[0]      = make_float4(a0.x, a1.x, a2.x, a3.x);   // v
    dst[rs]     = make_float4(a0.y, a1.y, a2.y, a3.y);   // v+1
    dst[2 * rs] = make_float4(a0.z, a1.z, a2.z, a3.z);   // v+2
    dst[3 * rs] = make_float4(a0.w, a1.w, a2.w, a3.w);   // v+3
}

// ---------------------------------------------------------------------------
// Kernel B: gather. Block: 128 threads, (b = blockIdx.y, 32 tokens).
// Token t (g=t>>2, j=t&3) lands at smem row R = 2g + (j&1) + 16*(j>>1).
// FOUR mbarriers keyed by gl = g&3 (each covers 8 tokens / 4 KB): thread
// (gl, q) waits ONLY its own barrier, then processes groups g=gl and g=gl+4.
// Per-thread progress is decoupled from the block's slowest TMA row.
// Phase 2: 4x conflict-free LDS.128, 4x4 register transpose, 4x STG.128
// (__stcs streaming writes; table reads carry L2 evict-last hint).
// ---------------------------------------------------------------------------
__global__ __launch_bounds__(128) void gather_kernel(
    const int* __restrict__ x, float* __restrict__ out) {
    __shared__ __align__(16) float tile[TOK * PITCH_F4 * 4];
    __shared__ __align__(8) unsigned long long mbar_storage[4];
    const float4* s4 = reinterpret_cast<const float4*>(tile);

    const int tid  = threadIdx.x;
    const int lane = tid & 31;
    const int wrp  = tid >> 5;
    const int b    = blockIdx.y;
    const int l0   = blockIdx.x * TOK;

    if (tid < 4) mbar_init(smem_u32(&mbar_storage[tid]), 1);
    __syncthreads();
    if (tid < 4) mbar_expect_tx(smem_u32(&mbar_storage[tid]), 8 * 512);
    if (tid < TOK) {
        const int v = x[(size_t)b * LL + l0 + tid];
        const int g = tid >> 2, j = tid & 3;
        const int R = 2 * g + (j & 1) + 16 * (j >> 1);
        bulk_g2s_el(smem_u32(tile) + R * PITCH_B, &g_wt[(size_t)v * PB], 512,
                    smem_u32(&mbar_storage[g & 3]));
    }

    const int gl = lane & 3;                     // token-group class (= barrier id)
    const int q  = wrp * 8 + (lane >> 2);        // p-quad 0..31
    float4* __restrict__ out4 = reinterpret_cast<float4*>(out);
    const size_t rstride = LL / 4;               // float4s per p-row

    // Wait only for this thread's 8 tokens (groups gl and gl+4).
    mbar_wait(smem_u32(&mbar_storage[gl]), 0);

    #pragma unroll
    for (int h = 0; h < 2; h++) {
        const int g = h * 4 + gl;                // token group (tokens 4g..4g+3)
        const int r0 = 2 * g;
        float4 f0 = s4[(r0 + 0)  * PITCH_F4 + q];   // j=0
        float4 f1 = s4[(r0 + 1)  * PITCH_F4 + q];   // j=1
        float4 f2 = s4[(r0 + 16) * PITCH_F4 + q];   // j=2
        float4 f3 = s4[(r0 + 17) * PITCH_F4 + q];   // j=3
        // Transpose: oj = tokens {4g..4g+3} at p = 4q+j.
        float4 o0 = make_float4(f0.x, f1.x, f2.x, f3.x);
        float4 o1 = make_float4(f0.y, f1.y, f2.y, f3.y);
        float4 o2 = make_float4(f0.z, f1.z, f2.z, f3.z);
        float4 o3 = make_float4(f0.w, f1.w, f2.w, f3.w);
        const size_t obase = ((size_t)b * PB + 4 * q) * rstride + (l0 >> 2) + g;
        __stcs(&out4[obase],               o0);
        __stcs(&out4[obase + rstride],     o1);
        __stcs(&out4[obase + 2 * rstride], o2);
        __stcs(&out4[obase + 3 * rstride], o3);
    }
}

// ---------------------------------------------------------------------------
// Launch: plain serial launches (PDL regressed — R8 post-mortem).
// ---------------------------------------------------------------------------
extern "C" void kernel_launch(void* const* d_in, const int* in_sizes, int n_in,
                              void* d_out, int out_size) {
    const int*   x    = (const int*)d_in[0];     // (64, 4096) int32
    const float* w_in = (const float*)d_in[1];   // (128, 32000) fp32
    float*       out  = (float*)d_out;           // (64, 128, 4096) fp32
    (void)in_sizes; (void)n_in; (void)out_size;

    transpose_kernel<<<dim3(VOC / 128, 4), 256>>>(w_in);
    gather_kernel<<<dim3(LL / TOK, BB), 128>>>(x, out);
}

// round 10
// speedup vs baseline: 1.5621x; 1.2541x over previous
#include <cuda_runtime.h>
#include <cuda_bf16.h>
#include <cstdint>

// out[b,p,l] = w_in[p, x[b,l]];  B=64, L=4096, P=128, VOCAB=32000, fp32.
#define PB   128
#define VOC  32000
#define BB   64
#define LL   4096
#define TOK  32            // tokens per gather block
#define PITCH_B 528        // smem row pitch: 512 B + 16 B pad = 33 float4 (odd)
#define PITCH_F4 33

// Transposed weight table w_t[v][p] (16.38 MB, mostly L2-resident).
__device__ __align__(512) float g_wt[(size_t)VOC * PB];

// ---------------- PTX helpers ----------------
__device__ __forceinline__ uint32_t smem_u32(const void* p) {
    return (uint32_t)__cvta_generic_to_shared(p);
}
__device__ __forceinline__ void mbar_init(uint32_t mbar, uint32_t cnt) {
    asm volatile("mbarrier.init.shared.b64 [%0], %1;" :: "r"(mbar), "r"(cnt) : "memory");
}
__device__ __forceinline__ void mbar_expect_tx(uint32_t mbar, uint32_t bytes) {
    asm volatile("mbarrier.arrive.expect_tx.shared.b64 _, [%0], %1;"
                 :: "r"(mbar), "r"(bytes) : "memory");
}
__device__ __forceinline__ void mbar_wait(uint32_t mbar, uint32_t parity) {
    asm volatile(
        "{\n\t"
        ".reg .pred P1;\n\t"
        "WAIT_LOOP_%=:\n\t"
        "mbarrier.try_wait.parity.acquire.cta.shared::cta.b64 P1, [%0], %1, 0x989680;\n\t"
        "@P1 bra.uni WAIT_DONE_%=;\n\t"
        "bra.uni WAIT_LOOP_%=;\n\t"
        "WAIT_DONE_%=:\n\t"
        "}"
        :: "r"(mbar), "r"(parity) : "memory");
}
__device__ __forceinline__ void bulk_g2s(uint32_t dst_smem, const void* src_gmem,
                                         uint32_t bytes, uint32_t mbar) {
    asm volatile(
        "cp.async.bulk.shared::cluster.global.mbarrier::complete_tx::bytes "
        "[%0], [%1], %2, [%3];"
        :: "r"(dst_smem), "l"(src_gmem), "r"(bytes), "r"(mbar) : "memory");
}

// ---------------------------------------------------------------------------
// Kernel A: transpose w_in(P, VOC) -> g_wt(VOC, P).  Zero smem, zero sync.
// Grid (250, 4): block covers 128 v x 32 p. Warp w owns p-quad p0 = by*32+4w;
// lane owns v-quad v0 + 4*lane. 4x coalesced LDG.128 reads, 4x4 register
// transpose, 4x STG.128 16 B-scatter writes (sector halves merged in L2 by
// the neighbor warp of the same block).
// ---------------------------------------------------------------------------
__global__ __launch_bounds__(256) void transpose_kernel(const float* __restrict__ w_in) {
    const int lane = threadIdx.x & 31;
    const int wrp  = threadIdx.x >> 5;           // 0..7
    const int v0   = blockIdx.x * 128;
    const int p0   = blockIdx.y * 32 + 4 * wrp;
    const int v    = v0 + 4 * lane;

    const size_t base = (size_t)p0 * VOC + v;
    const float4 a0 = *reinterpret_cast<const float4*>(&w_in[base]);
    const float4 a1 = *reinterpret_cast<const float4*>(&w_in[base + (size_t)VOC]);
    const float4 a2 = *reinterpret_cast<const float4*>(&w_in[base + 2 * (size_t)VOC]);
    const float4 a3 = *reinterpret_cast<const float4*>(&w_in[base + 3 * (size_t)VOC]);

    float4* __restrict__ dst = reinterpret_cast<float4*>(&g_wt[(size_t)v * PB + p0]);
    const size_t rs = PB / 4;                    // f4 stride between v-rows
    dst[0]      = make_float4(a0.x, a1.x, a2.x, a3.x);   // v
    dst[rs]     = make_float4(a0.y, a1.y, a2.y, a3.y);   // v+1
    dst[2 * rs] = make_float4(a0.z, a1.z, a2.z, a3.z);   // v+2
    dst[3 * rs] = make_float4(a0.w, a1.w, a2.w, a3.w);   // v+3
}

// ---------------------------------------------------------------------------
// Kernel B: gather (R7 structure; launch_bounds minBlocks=12 for deeper MLP).
// Block: 128 threads, (b = blockIdx.y, 32 tokens).
// Token t (g=t>>2, j=t&3) lands at smem row R = 2g + (j&1) + 16*(j>>1).
// Two mbarriers (tokens 0..15 / 16..31, 8 KB halves), all TMA up front;
// waits are block-uniform at the h-loop (lane-divergent waits regressed, R9).
// Phase 2 half h: thread (g = 4h + (lane&3), q = wrp*8 + (lane>>2)):
//   4x conflict-free LDS.128, 4x4 register transpose, 4x STG.128 (__stcs;
//   lanes 0-3 write 64 B-contiguous f4 runs -> full sectors).
// ---------------------------------------------------------------------------
__global__ __launch_bounds__(128, 12) void gather_kernel(
    const int* __restrict__ x, float* __restrict__ out) {
    __shared__ __align__(16) float tile[TOK * PITCH_F4 * 4];
    __shared__ __align__(8) unsigned long long mbar_storage[2];
    const float4* s4 = reinterpret_cast<const float4*>(tile);
    const uint32_t mbar0 = smem_u32(&mbar_storage[0]);
    const uint32_t mbar1 = smem_u32(&mbar_storage[1]);

    const int tid  = threadIdx.x;
    const int lane = tid & 31;
    const int wrp  = tid >> 5;
    const int b    = blockIdx.y;
    const int l0   = blockIdx.x * TOK;

    if (tid == 0) { mbar_init(mbar0, 1); mbar_init(mbar1, 1); }
    __syncthreads();
    if (tid == 0) {
        mbar_expect_tx(mbar0, 16 * 512);
        mbar_expect_tx(mbar1, 16 * 512);
    }
    if (tid < TOK) {
        const int v = x[(size_t)b * LL + l0 + tid];
        const int g = tid >> 2, j = tid & 3;
        const int R = 2 * g + (j & 1) + 16 * (j >> 1);
        bulk_g2s(smem_u32(tile) + R * PITCH_B, &g_wt[(size_t)v * PB], 512,
                 tid < 16 ? mbar0 : mbar1);
    }

    const int gl = lane & 3;                     // token-group within half
    const int q  = wrp * 8 + (lane >> 2);        // p-quad 0..31
    float4* __restrict__ out4 = reinterpret_cast<float4*>(out);
    const size_t rstride = LL / 4;               // float4s per p-row

    #pragma unroll
    for (int h = 0; h < 2; h++) {
        mbar_wait(h == 0 ? mbar0 : mbar1, 0);
        const int g = h * 4 + gl;                // token group (tokens 4g..4g+3)
        const int r0 = 2 * g;
        float4 f0 = s4[(r0 + 0)  * PITCH_F4 + q];   // j=0
        float4 f1 = s4[(r0 + 1)  * PITCH_F4 + q];   // j=1
        float4 f2 = s4[(r0 + 16) * PITCH_F4 + q];   // j=2
        float4 f3 = s4[(r0 + 17) * PITCH_F4 + q];   // j=3
        // Transpose: oj = tokens {4g..4g+3} at p = 4q+j.
        float4 o0 = make_float4(f0.x, f1.x, f2.x, f3.x);
        float4 o1 = make_float4(f0.y, f1.y, f2.y, f3.y);
        float4 o2 = make_float4(f0.z, f1.z, f2.z, f3.z);
        float4 o3 = make_float4(f0.w, f1.w, f2.w, f3.w);
        const size_t obase = ((size_t)b * PB + 4 * q) * rstride + (l0 >> 2) + g;
        __stcs(&out4[obase],               o0);
        __stcs(&out4[obase + rstride],     o1);
        __stcs(&out4[obase + 2 * rstride], o2);
        __stcs(&out4[obase + 3 * rstride], o3);
    }
}

// ---------------------------------------------------------------------------
// Launch: plain serial launches (PDL regressed — R8 post-mortem).
// ---------------------------------------------------------------------------
extern "C" void kernel_launch(void* const* d_in, const int* in_sizes, int n_in,
                              void* d_out, int out_size) {
    const int*   x    = (const int*)d_in[0];     // (64, 4096) int32
    const float* w_in = (const float*)d_in[1];   // (128, 32000) fp32
    float*       out  = (float*)d_out;           // (64, 128, 4096) fp32
    (void)in_sizes; (void)n_in; (void)out_size;

    transpose_kernel<<<dim3(VOC / 128, 4), 256>>>(w_in);
    gather_kernel<<<dim3(LL / TOK, BB), 128>>>(x, out);
}